// round 1
// baseline (speedup 1.0000x reference)
#include <cuda_runtime.h>
#include <cstdint>

// out[n,o,s] = sum_{c,k} din[n,c,s,k] * W[o,c,k] + b[o]
// din[n,c,s,0]=x[n,c,2s], din[n,c,s,1]=x[n,c,2s+1], din[n,c,s,2]=d[n,c,s]
// N=131072, ND=32, NPAIR=6, so x:[N,32,12] d:[N,32,6] W:[32,32,3] b:[32] out:[N,32,6] fp32

#define TB 16          // samples per block
#define KTOT 96        // 32 channels * 3 taps
#define JTOT 96        // TB * 6 slots
#define VSTRIDE 97     // pad: 97 == 1 (mod 32) -> conflict-free column reads

// W transposed: WT_g[kk*32 + o] = W[o][kk]  (12 KB, L1-resident)
__device__ float WT_g[KTOT * 32];

__global__ void prep_WT(const float* __restrict__ W) {
    int t = blockIdx.x * blockDim.x + threadIdx.x;
    if (t < 32 * KTOT) {
        int o  = t / KTOT;
        int kk = t - o * KTOT;
        WT_g[kk * 32 + o] = W[t];
    }
}

__global__ void __launch_bounds__(128)
dijet_kernel(const float* __restrict__ x, const float* __restrict__ d,
             const float* __restrict__ b, float* __restrict__ out, int n)
{
    // Column-major din tile: Vs[j * 97 + kk], j = local_sample*6 + slot
    __shared__ float Vs[JTOT * VSTRIDE];

    const int tid  = threadIdx.x;
    const int n0   = blockIdx.x * TB;
    const int nloc = (n - n0 < TB) ? (n - n0) : TB;

    // ---- stage x: 16 samples * 384 floats = 1536 float4 ----
    {
        const float4* x4 = reinterpret_cast<const float4*>(x) + (size_t)n0 * 96;
        const int nx4 = nloc * 96;
        for (int t = tid; t < nx4; t += 128) {
            float4 v = x4[t];
            int i   = t / 96;            // local sample
            int rem = t - i * 96;        // = c*3 + q
            int c   = rem / 3;
            int q   = rem - c * 3;
            int pos0 = q * 4;
            float vals[4] = {v.x, v.y, v.z, v.w};
            #pragma unroll
            for (int e = 0; e < 4; e++) {
                int pos = pos0 + e;                       // 0..11
                int s   = pos >> 1;
                int kk  = c * 3 + (pos & 1);
                Vs[(i * 6 + s) * VSTRIDE + kk] = vals[e];
            }
        }
    }
    // ---- stage d: 16 samples * 192 floats = 768 float4 ----
    {
        const float4* d4 = reinterpret_cast<const float4*>(d) + (size_t)n0 * 48;
        const int nd4 = nloc * 48;
        for (int t = tid; t < nd4; t += 128) {
            float4 v = d4[t];
            int i   = t / 48;
            int rem = t - i * 48;
            int f   = rem * 4;
            float vals[4] = {v.x, v.y, v.z, v.w};
            #pragma unroll
            for (int e = 0; e < 4; e++) {
                int ff = f + e;
                int c  = ff / 6;
                int s  = ff - c * 6;
                Vs[(i * 6 + s) * VSTRIDE + c * 3 + 2] = vals[e];
            }
        }
    }
    __syncthreads();

    // ---- compute: warp = 8 output rows, lane = 3 columns ----
    const int rg = tid >> 5;          // warp id: rows o0..o0+7
    const int cg = tid & 31;          // lane: columns j0..j0+2
    const int o0 = rg * 8;
    const int j0 = cg * 3;
    const int i  = cg >> 1;           // local sample (j0/6)
    const int s0 = (cg & 1) * 3;      // slot base 0 or 3

    // acc[p][jj] = f32x2 pair (out[o0+2p][j0+jj], out[o0+2p+1][j0+jj]), init = bias
    unsigned long long acc[4][3];
    {
        const ulonglong2* bp = reinterpret_cast<const ulonglong2*>(b + o0);
        ulonglong2 b01 = bp[0];
        ulonglong2 b23 = bp[1];
        #pragma unroll
        for (int jj = 0; jj < 3; jj++) {
            acc[0][jj] = b01.x; acc[1][jj] = b01.y;
            acc[2][jj] = b23.x; acc[3][jj] = b23.y;
        }
    }

    const float* vb = Vs + j0 * VSTRIDE;
    const float* wt = WT_g + o0;

    #pragma unroll 4
    for (int k = 0; k < KTOT; k++) {
        // 8 W values for rows o0..o0+7, pre-paired in memory (warp-uniform LDG.128 x2)
        const ulonglong2* wp = reinterpret_cast<const ulonglong2*>(wt + k * 32);
        ulonglong2 w01 = wp[0];
        ulonglong2 w23 = wp[1];
        #pragma unroll
        for (int jj = 0; jj < 3; jj++) {
            unsigned int vu = __float_as_uint(vb[jj * VSTRIDE + k]);
            unsigned long long vp;
            asm("mov.b64 %0, {%1, %1};" : "=l"(vp) : "r"(vu));
            asm("fma.rn.f32x2 %0, %1, %2, %0;" : "+l"(acc[0][jj]) : "l"(w01.x), "l"(vp));
            asm("fma.rn.f32x2 %0, %1, %2, %0;" : "+l"(acc[1][jj]) : "l"(w01.y), "l"(vp));
            asm("fma.rn.f32x2 %0, %1, %2, %0;" : "+l"(acc[2][jj]) : "l"(w23.x), "l"(vp));
            asm("fma.rn.f32x2 %0, %1, %2, %0;" : "+l"(acc[3][jj]) : "l"(w23.y), "l"(vp));
        }
    }

    // ---- store: thread owns out[n0+i][o0..o0+7][s0..s0+2] ----
    if (i < nloc) {
        float* op = out + ((size_t)(n0 + i) * 32 + o0) * 6 + s0;
        #pragma unroll
        for (int p = 0; p < 4; p++) {
            #pragma unroll
            for (int jj = 0; jj < 3; jj++) {
                unsigned int lo, hi;
                asm("mov.b64 {%0, %1}, %2;" : "=r"(lo), "=r"(hi) : "l"(acc[p][jj]));
                op[(2 * p)     * 6 + jj] = __uint_as_float(lo);
                op[(2 * p + 1) * 6 + jj] = __uint_as_float(hi);
            }
        }
    }
}

extern "C" void kernel_launch(void* const* d_in, const int* in_sizes, int n_in,
                              void* d_out, int out_size) {
    const float* x = (const float*)d_in[0];
    const float* d = (const float*)d_in[1];
    const float* W = (const float*)d_in[2];
    const float* b = (const float*)d_in[3];
    float* out = (float*)d_out;

    int n = in_sizes[0] / 384;   // N samples (x is [N,32,12])

    prep_WT<<<12, 256>>>(W);
    int nb = (n + TB - 1) / TB;
    dijet_kernel<<<nb, 128>>>(x, d, b, out, n);
}